// round 7
// baseline (speedup 1.0000x reference)
#include <cuda_runtime.h>
#include <cstdint>

// ---------------------------------------------------------------------------
// GAT fused: out[M,256] = x[M,256] @ w_l^T + (sum_k w_k * neigh[M,k,256]) @ w_r^T
// A[M,512] @ B[512,256], A = [x | aggr], B rows = [w_l ; w_r].
// mma.sync m16n8k8 tf32, fully synchronous. CTA tile 128x256, K chunks of 32.
// Static 48KB SMEM (no cudaFuncSetAttribute, no dynamic smem), XOR-swizzled,
// single-buffered with register prefetch of the DRAM-resident A/neigh stream.
// ---------------------------------------------------------------------------

#define M_TOTAL  262144      // T*N
#define DIN      256
#define DOUT     256
#define KNB      5
#define TILE_M   128
#define KC       32
#define NCHUNKS  16
#define THREADS  512

__device__ __forceinline__ uint32_t f2tf32(float f) {
    uint32_t u;
    asm("cvt.rna.tf32.f32 %0, %1;" : "=r"(u) : "f"(f));
    return u;
}

__device__ __forceinline__ void mma_tf32(float* d,
                                         uint32_t a0, uint32_t a1, uint32_t a2, uint32_t a3,
                                         uint32_t b0, uint32_t b1) {
    asm volatile(
        "mma.sync.aligned.m16n8k8.row.col.f32.tf32.tf32.f32 "
        "{%0,%1,%2,%3}, {%4,%5,%6,%7}, {%8,%9}, {%0,%1,%2,%3};"
        : "+f"(d[0]), "+f"(d[1]), "+f"(d[2]), "+f"(d[3])
        : "r"(a0), "r"(a1), "r"(a2), "r"(a3), "r"(b0), "r"(b1));
}

// XOR swizzle at float4 granularity within a 32-float row: group g of row r
// is stored at group (g ^ (r & 7)).
__device__ __forceinline__ int swz_idx(int row, int g, int e) {
    return row * KC + ((g ^ (row & 7)) << 2) + e;
}

__global__ void __launch_bounds__(THREADS, 1)
gat_mma_kernel(const float* __restrict__ x, const float* __restrict__ neigh,
               const float* __restrict__ wag, const float* __restrict__ wl,
               const float* __restrict__ wr, float* __restrict__ out)
{
    // 128*32 + 256*32 floats = 12288 * 4 B = 49152 B = 48 KB (static limit)
    __shared__ uint32_t sA[TILE_M * KC];
    __shared__ uint32_t sB[DOUT * KC];

    const int tid  = threadIdx.x;
    const int lane = tid & 31;
    const int wid  = tid >> 5;
    const int grp  = lane >> 2;      // 0..7
    const int qid  = lane & 3;       // 0..3
    const int warpM = wid >> 2;      // 0..3  (32 rows each)
    const int warpN = wid & 3;       // 0..3  (64 cols each)

    const float w0 = wag[0], w1 = wag[1], w2 = wag[2], w3 = wag[3], w4 = wag[4];
    const size_t mbase = (size_t)blockIdx.x * TILE_M;

    // A-stream prefetch: 2 float4 per thread per chunk
    const int a_r0 = tid >> 3;              // row for t=0 (0..63)
    const int a_r1 = (THREADS + tid) >> 3;  // row for t=1 (64..127)
    const int a_g  = tid & 7;               // float4 group within chunk

    float acc[2][8][4];
    #pragma unroll
    for (int i = 0; i < 2; ++i)
        #pragma unroll
        for (int j = 0; j < 8; ++j)
            #pragma unroll
            for (int q = 0; q < 4; ++q)
                acc[i][j][q] = 0.f;

    float4 pa0, pa1;   // prefetched A float4s (current chunk)

    // ---- prefetch chunk 0 of A (from x) ----
    {
        const int da = 0 * KC + a_g * 4;
        pa0 = *(const float4*)(x + (mbase + (size_t)a_r0) * DIN + da);
        pa1 = *(const float4*)(x + (mbase + (size_t)a_r1) * DIN + da);
    }

    #pragma unroll 1
    for (int c = 0; c < NCHUNKS; ++c) {
        // ---- store prefetched A to SMEM (swizzled, tf32) ----
        {
            uint4 v0 = make_uint4(f2tf32(pa0.x), f2tf32(pa0.y), f2tf32(pa0.z), f2tf32(pa0.w));
            uint4 v1 = make_uint4(f2tf32(pa1.x), f2tf32(pa1.y), f2tf32(pa1.z), f2tf32(pa1.w));
            *(uint4*)&sA[swz_idx(a_r0, a_g, 0)] = v0;
            *(uint4*)&sA[swz_idx(a_r1, a_g, 0)] = v1;
        }
        // ---- B tile: L2-resident weights, load+convert+store directly ----
        {
            const float* wsrc = (c < 8) ? wl : wr;
            const int db = (c & 7) * KC;
            #pragma unroll
            for (int t = 0; t < 4; ++t) {
                const int idx = t * THREADS + tid;
                const int n = idx >> 3, g = idx & 7;
                float4 v = *(const float4*)(wsrc + (size_t)n * DIN + db + g * 4);
                uint4 pv = make_uint4(f2tf32(v.x), f2tf32(v.y), f2tf32(v.z), f2tf32(v.w));
                *(uint4*)&sB[swz_idx(n, g, 0)] = pv;
            }
        }
        __syncthreads();

        // ---- prefetch next chunk of A (LDGs fly during the MMAs below) ----
        if (c + 1 < NCHUNKS) {
            const int cn = c + 1;
            if (cn < 8) {
                const int da = cn * KC + a_g * 4;
                pa0 = *(const float4*)(x + (mbase + (size_t)a_r0) * DIN + da);
                pa1 = *(const float4*)(x + (mbase + (size_t)a_r1) * DIN + da);
            } else {
                const int da = (cn - 8) * KC + a_g * 4;
                const float4* np0 =
                    (const float4*)(neigh + (mbase + (size_t)a_r0) * (KNB * DIN) + da);
                const float4* np1 =
                    (const float4*)(neigh + (mbase + (size_t)a_r1) * (KNB * DIN) + da);
                float4 u0 = np0[0], u1 = np0[DIN/4], u2 = np0[2*(DIN/4)],
                       u3 = np0[3*(DIN/4)], u4 = np0[4*(DIN/4)];
                float4 t0 = np1[0], t1 = np1[DIN/4], t2 = np1[2*(DIN/4)],
                       t3 = np1[3*(DIN/4)], t4 = np1[4*(DIN/4)];
                pa0.x = w0*u0.x + w1*u1.x + w2*u2.x + w3*u3.x + w4*u4.x;
                pa0.y = w0*u0.y + w1*u1.y + w2*u2.y + w3*u3.y + w4*u4.y;
                pa0.z = w0*u0.z + w1*u1.z + w2*u2.z + w3*u3.z + w4*u4.z;
                pa0.w = w0*u0.w + w1*u1.w + w2*u2.w + w3*u3.w + w4*u4.w;
                pa1.x = w0*t0.x + w1*t1.x + w2*t2.x + w3*t3.x + w4*t4.x;
                pa1.y = w0*t0.y + w1*t1.y + w2*t2.y + w3*t3.y + w4*t4.y;
                pa1.z = w0*t0.z + w1*t1.z + w2*t2.z + w3*t3.z + w4*t4.z;
                pa1.w = w0*t0.w + w1*t1.w + w2*t2.w + w3*t3.w + w4*t4.w;
            }
        }

        // ---- compute this chunk from SMEM ----
        #pragma unroll
        for (int ks = 0; ks < 4; ++ks) {
            const int g0 = 2 * ks;           // float4 groups g0, g0+1 hold k0..k0+7
            uint32_t a[2][4];
            #pragma unroll
            for (int i = 0; i < 2; ++i) {
                const int r = warpM * 32 + i * 16 + grp;   // r & 7 == grp
                a[i][0] = sA[swz_idx(r,     g0,     qid)];
                a[i][1] = sA[swz_idx(r + 8, g0,     qid)];
                a[i][2] = sA[swz_idx(r,     g0 + 1, qid)];
                a[i][3] = sA[swz_idx(r + 8, g0 + 1, qid)];
            }
            #pragma unroll
            for (int j = 0; j < 8; ++j) {
                const int n = warpN * 64 + j * 8 + grp;    // n & 7 == grp
                const uint32_t b0 = sB[swz_idx(n, g0,     qid)];
                const uint32_t b1 = sB[swz_idx(n, g0 + 1, qid)];
                mma_tf32(acc[0][j], a[0][0], a[0][1], a[0][2], a[0][3], b0, b1);
                mma_tf32(acc[1][j], a[1][0], a[1][1], a[1][2], a[1][3], b0, b1);
            }
        }
        __syncthreads();
    }

    // ---- epilogue: m16n8 accumulator layout -> out ----
    #pragma unroll
    for (int i = 0; i < 2; ++i) {
        const size_t row = mbase + warpM * 32 + i * 16 + grp;
        #pragma unroll
        for (int j = 0; j < 8; ++j) {
            const int col = warpN * 64 + j * 8 + qid * 2;
            *(float2*)&out[row * DOUT + col] =
                make_float2(acc[i][j][0], acc[i][j][1]);
            *(float2*)&out[(row + 8) * DOUT + col] =
                make_float2(acc[i][j][2], acc[i][j][3]);
        }
    }
}

extern "C" void kernel_launch(void* const* d_in, const int* in_sizes, int n_in,
                              void* d_out, int out_size) {
    const float* x     = (const float*)d_in[0];   // [T,N,256]
    const float* neigh = (const float*)d_in[1];   // [T,N,5,256]
    const float* wag   = (const float*)d_in[2];   // [1,5]
    const float* wl    = (const float*)d_in[3];   // [256,256]
    const float* wr    = (const float*)d_in[4];   // [256,256]
    float* out         = (float*)d_out;           // [M,256]

    gat_mma_kernel<<<M_TOTAL / TILE_M, THREADS>>>(x, neigh, wag, wl, wr, out);
}